// round 8
// baseline (speedup 1.0000x reference)
#include <cuda_runtime.h>
#include <cuda_fp16.h>
#include <cuda_fp8.h>
#include <cstdint>
#include <stdint.h>
#include <math.h>

// Problem constants (fixed by the reference)
constexpr int NODES  = 100000;
constexpr int EDGES  = 1600000;
constexpr int GRAPHS = 64;
constexpr int DH     = 128;   // DI == DH == 128
constexpr int DOUT   = 10;

constexpr int NB = (NODES + 255) / 256;   // scan blocks (391)

// Scratch (device globals: allocation-free rule)
__device__ unsigned char g_m8 [NODES * 128]; // messages m[i]=(h@W)*dinv[i], e4m3 (12.8MB)
__device__ __half  g_aggh[NODES * 128];   // aggregate, fp16 (fp32 accum in regs)
__device__ __half  g_wh  [3 * 128 * 128]; // all 3 layers' weights, fp16, swizzled
__device__ int     g_deg [NODES];
__device__ float   g_dinv[NODES];
__device__ int     g_rowptr[NODES];       // CSR row start (end = start + deg)
__device__ int     g_cursor[NODES];
__device__ int     g_csr[EDGES];          // src indices grouped by dst
__device__ int     g_bsum[512];

// ---------------------------------------------------------------------------
// Degree
// ---------------------------------------------------------------------------
__global__ void k_zero_deg() {
    int i = blockIdx.x * blockDim.x + threadIdx.x;
    if (i < NODES) g_deg[i] = 0;
}

__global__ void k_count_deg(const int* __restrict__ ei) {   // 2 edges/thread
    int e2 = blockIdx.x * blockDim.x + threadIdx.x;
    if (e2 < EDGES / 2) {
        int2 d = ((const int2*)(ei + EDGES))[e2];
        atomicAdd(&g_deg[d.x], 1);
        atomicAdd(&g_deg[d.y], 1);
    }
}

// ---------------------------------------------------------------------------
// CSR build: 3-kernel exclusive scan of g_deg (+dinv fused), atomic-cursor fill.
// ---------------------------------------------------------------------------
__global__ void k_scan_blocksum() {          // grid NB, block 256
    int i = blockIdx.x * 256 + threadIdx.x;
    int v = (i < NODES) ? g_deg[i] : 0;
    __shared__ int wsum[8];
#pragma unroll
    for (int off = 16; off > 0; off >>= 1) v += __shfl_xor_sync(~0u, v, off);
    if ((threadIdx.x & 31) == 0) wsum[threadIdx.x >> 5] = v;
    __syncthreads();
    if (threadIdx.x < 8) {
        int s = wsum[threadIdx.x];
#pragma unroll
        for (int off = 4; off > 0; off >>= 1) s += __shfl_xor_sync(0xFFu, s, off);
        if (threadIdx.x == 0) g_bsum[blockIdx.x] = s;
    }
}

__global__ void k_scan_top() {               // single block of 512
    __shared__ int sh[512];
    int t = threadIdx.x;
    int v = (t < NB) ? g_bsum[t] : 0;
    sh[t] = v;
    __syncthreads();
    for (int off = 1; off < 512; off <<= 1) {
        int add = (t >= off) ? sh[t - off] : 0;
        __syncthreads();
        sh[t] += add;
        __syncthreads();
    }
    if (t < NB) g_bsum[t] = sh[t] - v;       // exclusive
}

__global__ void k_scan_apply() {             // grid NB, block 256
    __shared__ int sh[256];
    int i = blockIdx.x * 256 + threadIdx.x;
    int t = threadIdx.x;
    int v = (i < NODES) ? g_deg[i] : 0;
    sh[t] = v;
    __syncthreads();
    for (int off = 1; off < 256; off <<= 1) {
        int add = (t >= off) ? sh[t - off] : 0;
        __syncthreads();
        sh[t] += add;
        __syncthreads();
    }
    if (i < NODES) {
        int start = g_bsum[blockIdx.x] + sh[t] - v;
        g_rowptr[i] = start;
        g_cursor[i] = start;
        g_dinv[i] = rsqrtf((float)(v + 1));  // +1 self loop (fused here)
    }
}

__global__ void k_csr_fill(const int* __restrict__ ei) {    // 2 edges/thread
    int e2 = blockIdx.x * blockDim.x + threadIdx.x;
    if (e2 < EDGES / 2) {
        int2 s = ((const int2*)ei)[e2];
        int2 d = ((const int2*)(ei + EDGES))[e2];
        int p0 = atomicAdd(&g_cursor[d.x], 1);
        g_csr[p0] = s.x;
        int p1 = atomicAdd(&g_cursor[d.y], 1);
        g_csr[p1] = s.y;
    }
}

// ---------------------------------------------------------------------------
// Weight pre-convert (all 3 layers): fp32 -> fp16, ldmatrix-swizzled.
// grid 24, block 256 (3 x 2048 chunks of 16B).
// ---------------------------------------------------------------------------
__global__ void k_wconv_all(const float* __restrict__ W1,
                            const float* __restrict__ W2,
                            const float* __restrict__ W3) {
    int gchunk = blockIdx.x * 256 + threadIdx.x;   // 0..6143
    int layer = gchunk >> 11;                       // 0..2
    int chunk = gchunk & 2047;
    int row = chunk >> 4, cn = chunk & 15;
    const float* W = (layer == 0) ? W1 : (layer == 1) ? W2 : W3;
    const float4* W4 = (const float4*)W;
    float4 v0 = W4[row * 32 + cn * 2];
    float4 v1 = W4[row * 32 + cn * 2 + 1];
    union { uint4 u; __half2 h[4]; } pk;
    pk.h[0] = __floats2half2_rn(v0.x, v0.y);
    pk.h[1] = __floats2half2_rn(v0.z, v0.w);
    pk.h[2] = __floats2half2_rn(v1.x, v1.y);
    pk.h[3] = __floats2half2_rn(v1.z, v1.w);
    *(uint4*)(g_wh + layer * 128 * 128 + row * 128 + ((cn ^ (row & 7)) << 3)) = pk.u;
}

// ---------------------------------------------------------------------------
// Tensor-core GEMM: m_row = (pre(in_row)) @ W * dinv[row] -> e4m3 g_m8.
// pre(in) = in                      (use_pre == 0, first layer reads fp32 x)
// pre(in) = relu(in*dinv[row] + b)  (use_pre == 1, reads fp16 g_aggh)
// Each block: loads sB once, processes TWO 64-row A tiles.
// Epilogue stages e4m3 pairs in sA (reused), then writes 16B-coalesced.
// ---------------------------------------------------------------------------
__device__ __forceinline__ uint32_t s2u(const void* p) {
    return (uint32_t)__cvta_generic_to_shared(p);
}

__global__ void __launch_bounds__(256) k_gemm_tc(const float* __restrict__ xin,
                                                 int use_pre, int wlayer,
                                                 const float* __restrict__ bias) {
    __shared__ __align__(16) __half sA[64 * 128];
    __shared__ __align__(16) __half sB[128 * 128];
    const int tid = threadIdx.x;

    // ---- B: raw copy of pre-swizzled fp16 weights (2048 x 16B).
    const uint4* wsrc = (const uint4*)(g_wh + wlayer * 128 * 128);
    uint4* bdst = (uint4*)sB;
#pragma unroll
    for (int i = 0; i < 8; i++) bdst[i * 256 + tid] = __ldg(wsrc + i * 256 + tid);

    const int lane = tid & 31, wid = tid >> 5;
    const int wm = wid & 1;        // 2 warps over m (32 rows each)
    const int wn = wid >> 1;       // 4 warps over n (32 cols each)
    const uint32_t sAu = s2u(sA), sBu = s2u(sB);

    for (int half = 0; half < 2; half++) {
        const int r0 = blockIdx.x * 128 + half * 64;
        if (half) __syncthreads();     // all reads of previous epilogue stage done

        // ---- A tile [64][128] with fused pre-transform. 1024 chunks of 16B.
#pragma unroll
        for (int i = 0; i < 4; i++) {
            int chunk = i * 256 + tid;
            int row = chunk >> 4, cn = chunk & 15;
            int grow = r0 + row;
            union { uint4 u; __half2 h[4]; } pk;
            if (grow >= NODES) {
                pk.u = make_uint4(0, 0, 0, 0);
            } else if (use_pre) {
                union { uint4 u; __half2 h[4]; } in;
                in.u = *(const uint4*)(g_aggh + grow * 128 + cn * 8);
                float di = g_dinv[grow];
                const float* bp = bias + cn * 8;
                float2 f0 = __half22float2(in.h[0]);
                float2 f1 = __half22float2(in.h[1]);
                float2 f2 = __half22float2(in.h[2]);
                float2 f3 = __half22float2(in.h[3]);
                f0.x = fmaxf(fmaf(f0.x, di, bp[0]), 0.f);
                f0.y = fmaxf(fmaf(f0.y, di, bp[1]), 0.f);
                f1.x = fmaxf(fmaf(f1.x, di, bp[2]), 0.f);
                f1.y = fmaxf(fmaf(f1.y, di, bp[3]), 0.f);
                f2.x = fmaxf(fmaf(f2.x, di, bp[4]), 0.f);
                f2.y = fmaxf(fmaf(f2.y, di, bp[5]), 0.f);
                f3.x = fmaxf(fmaf(f3.x, di, bp[6]), 0.f);
                f3.y = fmaxf(fmaf(f3.y, di, bp[7]), 0.f);
                pk.h[0] = __floats2half2_rn(f0.x, f0.y);
                pk.h[1] = __floats2half2_rn(f1.x, f1.y);
                pk.h[2] = __floats2half2_rn(f2.x, f2.y);
                pk.h[3] = __floats2half2_rn(f3.x, f3.y);
            } else {
                float4 v0 = ((const float4*)xin)[grow * 32 + cn * 2];
                float4 v1 = ((const float4*)xin)[grow * 32 + cn * 2 + 1];
                pk.h[0] = __floats2half2_rn(v0.x, v0.y);
                pk.h[1] = __floats2half2_rn(v0.z, v0.w);
                pk.h[2] = __floats2half2_rn(v1.x, v1.y);
                pk.h[3] = __floats2half2_rn(v1.z, v1.w);
            }
            *(uint4*)(sA + row * 128 + ((cn ^ (row & 7)) << 3)) = pk.u;
        }
        __syncthreads();

        float c[2][4][4];
#pragma unroll
        for (int mt = 0; mt < 2; mt++)
#pragma unroll
            for (int nt = 0; nt < 4; nt++)
#pragma unroll
                for (int q = 0; q < 4; q++) c[mt][nt][q] = 0.f;

#pragma unroll
        for (int ks = 0; ks < 8; ks++) {
            uint32_t a[2][4];
#pragma unroll
            for (int mt = 0; mt < 2; mt++) {
                int r = wm * 32 + mt * 16 + (lane & 15);
                int ch = ks * 2 + (lane >> 4);
                uint32_t addr = sAu + (r << 8) + ((ch ^ (r & 7)) << 4);
                asm volatile("ldmatrix.sync.aligned.m8n8.x4.shared.b16 {%0,%1,%2,%3}, [%4];"
                             : "=r"(a[mt][0]), "=r"(a[mt][1]), "=r"(a[mt][2]), "=r"(a[mt][3])
                             : "r"(addr));
            }
            uint32_t b[4][2];
#pragma unroll
            for (int nt = 0; nt < 4; nt++) {
                int r = ks * 16 + (lane & 15);
                int ch = wn * 4 + nt;
                uint32_t addr = sBu + (r << 8) + ((ch ^ (r & 7)) << 4);
                asm volatile("ldmatrix.sync.aligned.m8n8.x2.trans.shared.b16 {%0,%1}, [%2];"
                             : "=r"(b[nt][0]), "=r"(b[nt][1])
                             : "r"(addr));
            }
#pragma unroll
            for (int mt = 0; mt < 2; mt++)
#pragma unroll
                for (int nt = 0; nt < 4; nt++) {
                    asm volatile(
                        "mma.sync.aligned.m16n8k16.row.col.f32.f16.f16.f32 "
                        "{%0,%1,%2,%3}, {%4,%5,%6,%7}, {%8,%9}, {%0,%1,%2,%3};"
                        : "+f"(c[mt][nt][0]), "+f"(c[mt][nt][1]),
                          "+f"(c[mt][nt][2]), "+f"(c[mt][nt][3])
                        : "r"(a[mt][0]), "r"(a[mt][1]), "r"(a[mt][2]), "r"(a[mt][3]),
                          "r"(b[nt][0]), "r"(b[nt][1]));
                }
        }

        // ---- Epilogue: * dinv[row], pack e4m3, stage in sA, coalesced store.
        __syncthreads();   // all warps done reading sA (ldmatrix)
        unsigned short* stage = (unsigned short*)sA;  // [64 rows][64 pairs]
#pragma unroll
        for (int mt = 0; mt < 2; mt++) {
#pragma unroll
            for (int hf = 0; hf < 2; hf++) {
                int rloc = wm * 32 + mt * 16 + (lane >> 2) + hf * 8;  // 0..63
                int grow = r0 + rloc;
                float di = (grow < NODES) ? g_dinv[grow] : 0.f;
#pragma unroll
                for (int nt = 0; nt < 4; nt++) {
                    int c2 = wn * 16 + nt * 4 + (lane & 3);           // pair idx 0..63
                    float2 f = make_float2(c[mt][nt][hf * 2 + 0] * di,
                                           c[mt][nt][hf * 2 + 1] * di);
                    stage[rloc * 64 + c2] =
                        __nv_cvt_float2_to_fp8x2(f, __NV_SATFINITE, __NV_E4M3);
                }
            }
        }
        __syncthreads();
        // copy out 512 x 16B (64 rows x 128B)
        const uint4* st4 = (const uint4*)sA;
#pragma unroll
        for (int i = 0; i < 2; i++) {
            int idx = i * 256 + tid;            // 0..511
            int row = idx >> 3, part = idx & 7;
            int grow = r0 + row;
            if (grow < NODES)
                ((uint4*)g_m8)[grow * 8 + part] = st4[idx];
        }
    }
}

// ---------------------------------------------------------------------------
// CSR aggregation: agg[n] = m[n] (self loop) + sum_{src in csr row n} m[src].
// One warp per node; lane owns 4 features = 4 e4m3 bytes (uint32 gather).
// Warp gather = 128B = ONE L2 line per neighbor. fp32 accumulate, fp16 store.
// ---------------------------------------------------------------------------
__device__ __forceinline__ void acc_e4m3x4(uint32_t u, float& a0, float& a1,
                                           float& a2, float& a3) {
    __half2_raw h0 = __nv_cvt_fp8x2_to_halfraw2(
        (__nv_fp8x2_storage_t)(u & 0xFFFFu), __NV_E4M3);
    __half2_raw h1 = __nv_cvt_fp8x2_to_halfraw2(
        (__nv_fp8x2_storage_t)(u >> 16), __NV_E4M3);
    float2 f0 = __half22float2(*reinterpret_cast<__half2*>(&h0));
    float2 f1 = __half22float2(*reinterpret_cast<__half2*>(&h1));
    a0 += f0.x; a1 += f0.y; a2 += f1.x; a3 += f1.y;
}

__global__ void __launch_bounds__(256) k_aggregate() {
    int node = blockIdx.x * 8 + (threadIdx.x >> 5);
    if (node >= NODES) return;
    int lane = threadIdx.x & 31;

    const unsigned char* m8 = g_m8;
    const int* __restrict__ csr = g_csr;

    float a0 = 0.f, a1 = 0.f, a2 = 0.f, a3 = 0.f;
    // self loop
    acc_e4m3x4(*(const uint32_t*)(m8 + node * 128 + lane * 4), a0, a1, a2, a3);

    int i = g_rowptr[node];
    int e = i + g_deg[node];

    for (; i + 8 <= e; i += 8) {
        int s[8];
#pragma unroll
        for (int j = 0; j < 8; j++) s[j] = __ldg(csr + i + j);
        uint32_t u[8];
#pragma unroll
        for (int j = 0; j < 8; j++)
            u[j] = *(const uint32_t*)(m8 + s[j] * 128 + lane * 4);
#pragma unroll
        for (int j = 0; j < 8; j++) acc_e4m3x4(u[j], a0, a1, a2, a3);
    }
    for (; i + 2 <= e; i += 2) {
        int s0 = __ldg(csr + i), s1 = __ldg(csr + i + 1);
        uint32_t u0 = *(const uint32_t*)(m8 + s0 * 128 + lane * 4);
        uint32_t u1 = *(const uint32_t*)(m8 + s1 * 128 + lane * 4);
        acc_e4m3x4(u0, a0, a1, a2, a3);
        acc_e4m3x4(u1, a0, a1, a2, a3);
    }
    if (i < e) {
        int s0 = __ldg(csr + i);
        acc_e4m3x4(*(const uint32_t*)(m8 + s0 * 128 + lane * 4), a0, a1, a2, a3);
    }

    union { uint2 u; __half2 h[2]; } outp;
    outp.h[0] = __floats2half2_rn(a0, a1);
    outp.h[1] = __floats2half2_rn(a2, a3);
    *(uint2*)(g_aggh + node * 128 + lane * 4) = outp.u;
}

// ---------------------------------------------------------------------------
// Fused mean pool + head: block per graph, 128 threads.
// ---------------------------------------------------------------------------
__global__ void __launch_bounds__(128) k_pool_head(const int* __restrict__ batch,
                                                   const float* __restrict__ b3,
                                                   const float* __restrict__ Wl,
                                                   const float* __restrict__ bl,
                                                   float* __restrict__ out) {
    __shared__ float hg[DH];
    int g = blockIdx.x, t = threadIdx.x;
    int lo = 0, hi = NODES;
    while (lo < hi) { int m = (lo + hi) >> 1; if (batch[m] < g) lo = m + 1; else hi = m; }
    int s = lo;
    hi = NODES;
    while (lo < hi) { int m = (lo + hi) >> 1; if (batch[m] <= g) lo = m + 1; else hi = m; }
    int e = lo;

    float sum = 0.f;
    for (int n = s; n < e; n++)
        sum = fmaf(__half2float(g_aggh[n * 128 + t]), g_dinv[n], sum);
    int cnt = e - s;
    hg[t] = (cnt > 0) ? (sum / (float)cnt + b3[t]) : 0.f;
    __syncthreads();

    if (t < 32) {
        int lane = t;
        float acc[DOUT];
#pragma unroll
        for (int c = 0; c < DOUT; c++) acc[c] = 0.f;
        for (int k = lane; k < DH; k += 32) {
            float h = hg[k];
#pragma unroll
            for (int c = 0; c < DOUT; c++) acc[c] = fmaf(h, Wl[k * DOUT + c], acc[c]);
        }
#pragma unroll
        for (int off = 16; off > 0; off >>= 1)
#pragma unroll
            for (int c = 0; c < DOUT; c++)
                acc[c] += __shfl_xor_sync(0xFFFFFFFFu, acc[c], off);

        float mx = -1e30f;
#pragma unroll
        for (int c = 0; c < DOUT; c++) { acc[c] += bl[c]; mx = fmaxf(mx, acc[c]); }
        float ssum = 0.f;
#pragma unroll
        for (int c = 0; c < DOUT; c++) { acc[c] = expf(acc[c] - mx); ssum += acc[c]; }
        if (lane < DOUT) out[g * DOUT + lane] = acc[lane] / ssum;
    }
}

// ---------------------------------------------------------------------------
extern "C" void kernel_launch(void* const* d_in, const int* in_sizes, int n_in,
                              void* d_out, int out_size) {
    const float* x     = (const float*)d_in[0];
    const int*   ei    = (const int*)  d_in[1];
    const int*   batch = (const int*)  d_in[2];
    const float* W1 = (const float*)d_in[3];
    const float* b1 = (const float*)d_in[4];
    const float* W2 = (const float*)d_in[5];
    const float* b2 = (const float*)d_in[6];
    const float* W3 = (const float*)d_in[7];
    const float* b3 = (const float*)d_in[8];
    const float* Wl = (const float*)d_in[9];
    const float* bl = (const float*)d_in[10];
    float* out = (float*)d_out;

    const int gemm_grid = (NODES + 127) / 128;
    const int agg_grid  = (NODES + 7) / 8;

    // weights (independent of graph structure work below)
    k_wconv_all<<<24, 256>>>(W1, W2, W3);

    // degrees
    k_zero_deg <<<(NODES + 255) / 256, 256>>>();
    k_count_deg<<<(EDGES / 2 + 255) / 256, 256>>>(ei);

    // CSR build (by dst) + dinv
    k_scan_blocksum<<<NB, 256>>>();
    k_scan_top     <<<1, 512>>>();
    k_scan_apply   <<<NB, 256>>>();
    k_csr_fill     <<<(EDGES / 2 + 255) / 256, 256>>>(ei);

    // Layer 1
    k_gemm_tc  <<<gemm_grid, 256>>>(x, 0, 0, nullptr);
    k_aggregate<<<agg_grid, 256>>>();
    // Layer 2
    k_gemm_tc  <<<gemm_grid, 256>>>(nullptr, 1, 1, b1);
    k_aggregate<<<agg_grid, 256>>>();
    // Layer 3
    k_gemm_tc  <<<gemm_grid, 256>>>(nullptr, 1, 2, b2);
    k_aggregate<<<agg_grid, 256>>>();

    k_pool_head<<<GRAPHS, 128>>>(batch, b3, Wl, bl, out);
}

// round 9
// speedup vs baseline: 1.0031x; 1.0031x over previous
#include <cuda_runtime.h>
#include <cuda_fp16.h>
#include <cstdint>
#include <stdint.h>
#include <math.h>

// Problem constants (fixed by the reference)
constexpr int NODES  = 100000;
constexpr int EDGES  = 1600000;
constexpr int GRAPHS = 64;
constexpr int DH     = 128;   // DI == DH == 128
constexpr int DOUT   = 10;

constexpr int NB = (NODES + 255) / 256;   // alloc blocks (391)

// Scratch (device globals: allocation-free rule)
__device__ __half  g_mh  [NODES * 128];   // messages m[i] = (h@W)*dinv[i], fp16
__device__ __half  g_aggh[NODES * 128];   // aggregate, fp16 (fp32 accum in regs)
__device__ __half  g_wh  [3 * 128 * 128]; // all 3 layers' weights, fp16, swizzled
__device__ int     g_deg [NODES];
__device__ float   g_dinv[NODES];
__device__ int     g_rowptr[NODES];       // CSR row start (end = start + deg)
__device__ int     g_cursor[NODES];
__device__ int     g_csr[EDGES];          // src indices grouped by dst
__device__ int     g_total;               // global CSR allocation cursor

// ---------------------------------------------------------------------------
// Degree
// ---------------------------------------------------------------------------
__global__ void k_zero_deg() {
    int i = blockIdx.x * blockDim.x + threadIdx.x;
    if (i < NODES) g_deg[i] = 0;
    if (i == 0) g_total = 0;
}

__global__ void k_count_deg(const int* __restrict__ ei) {   // 4 edges/thread
    int e4 = blockIdx.x * blockDim.x + threadIdx.x;
    if (e4 < EDGES / 4) {
        int4 d = ((const int4*)(ei + EDGES))[e4];
        atomicAdd(&g_deg[d.x], 1);
        atomicAdd(&g_deg[d.y], 1);
        atomicAdd(&g_deg[d.z], 1);
        atomicAdd(&g_deg[d.w], 1);
    }
}

// ---------------------------------------------------------------------------
// CSR allocation: single kernel. Block-local inclusive scan of degrees, one
// atomicAdd for the block's base (allocation order across blocks is arbitrary
// but always a valid disjoint layout). Also emits dinv.
// ---------------------------------------------------------------------------
__global__ void k_alloc() {                  // grid NB, block 256
    __shared__ int sh[256];
    __shared__ int sbase;
    int i = blockIdx.x * 256 + threadIdx.x;
    int t = threadIdx.x;
    int v = (i < NODES) ? g_deg[i] : 0;
    sh[t] = v;
    __syncthreads();
    for (int off = 1; off < 256; off <<= 1) {
        int add = (t >= off) ? sh[t - off] : 0;
        __syncthreads();
        sh[t] += add;
        __syncthreads();
    }
    if (t == 255) sbase = atomicAdd(&g_total, sh[255]);
    __syncthreads();
    if (i < NODES) {
        int start = sbase + sh[t] - v;       // exclusive within block + base
        g_rowptr[i] = start;
        g_cursor[i] = start;
        g_dinv[i] = rsqrtf((float)(v + 1));  // +1 self loop
    }
}

__global__ void k_csr_fill(const int* __restrict__ ei) {    // 4 edges/thread
    int e4 = blockIdx.x * blockDim.x + threadIdx.x;
    if (e4 < EDGES / 4) {
        int4 s = ((const int4*)ei)[e4];
        int4 d = ((const int4*)(ei + EDGES))[e4];
        g_csr[atomicAdd(&g_cursor[d.x], 1)] = s.x;
        g_csr[atomicAdd(&g_cursor[d.y], 1)] = s.y;
        g_csr[atomicAdd(&g_cursor[d.z], 1)] = s.z;
        g_csr[atomicAdd(&g_cursor[d.w], 1)] = s.w;
    }
}

// ---------------------------------------------------------------------------
// Weight pre-convert (all 3 layers): fp32 -> fp16, ldmatrix-swizzled.
// grid 24, block 256 (3 x 2048 chunks of 16B).
// ---------------------------------------------------------------------------
__global__ void k_wconv_all(const float* __restrict__ W1,
                            const float* __restrict__ W2,
                            const float* __restrict__ W3) {
    int gchunk = blockIdx.x * 256 + threadIdx.x;   // 0..6143
    int layer = gchunk >> 11;                       // 0..2
    int chunk = gchunk & 2047;
    int row = chunk >> 4, cn = chunk & 15;
    const float* W = (layer == 0) ? W1 : (layer == 1) ? W2 : W3;
    const float4* W4 = (const float4*)W;
    float4 v0 = W4[row * 32 + cn * 2];
    float4 v1 = W4[row * 32 + cn * 2 + 1];
    union { uint4 u; __half2 h[4]; } pk;
    pk.h[0] = __floats2half2_rn(v0.x, v0.y);
    pk.h[1] = __floats2half2_rn(v0.z, v0.w);
    pk.h[2] = __floats2half2_rn(v1.x, v1.y);
    pk.h[3] = __floats2half2_rn(v1.z, v1.w);
    *(uint4*)(g_wh + layer * 128 * 128 + row * 128 + ((cn ^ (row & 7)) << 3)) = pk.u;
}

// ---------------------------------------------------------------------------
// Tensor-core GEMM: m_row = (pre(in_row)) @ W * dinv[row] -> fp16 g_mh.
// pre(in) = in                      (use_pre == 0, first layer reads fp32 x)
// pre(in) = relu(in*dinv[row] + b)  (use_pre == 1, reads fp16 g_aggh)
// Each block: loads sB once, processes TWO 64-row A tiles.
// 8 warps, 2(m) x 4(n). XOR-swizzled smem, ldmatrix + mma.m16n8k16.
// ---------------------------------------------------------------------------
__device__ __forceinline__ uint32_t s2u(const void* p) {
    return (uint32_t)__cvta_generic_to_shared(p);
}

__global__ void __launch_bounds__(256) k_gemm_tc(const float* __restrict__ xin,
                                                 int use_pre, int wlayer,
                                                 const float* __restrict__ bias) {
    __shared__ __align__(16) __half sA[64 * 128];
    __shared__ __align__(16) __half sB[128 * 128];
    const int tid = threadIdx.x;

    // ---- B: raw copy of pre-swizzled fp16 weights (2048 x 16B).
    const uint4* wsrc = (const uint4*)(g_wh + wlayer * 128 * 128);
    uint4* bdst = (uint4*)sB;
#pragma unroll
    for (int i = 0; i < 8; i++) bdst[i * 256 + tid] = __ldg(wsrc + i * 256 + tid);

    const int lane = tid & 31, wid = tid >> 5;
    const int wm = wid & 1;        // 2 warps over m (32 rows each)
    const int wn = wid >> 1;       // 4 warps over n (32 cols each)
    const uint32_t sAu = s2u(sA), sBu = s2u(sB);

    for (int half = 0; half < 2; half++) {
        const int r0 = blockIdx.x * 128 + half * 64;
        if (half) __syncthreads();     // all reads of previous sA done

        // ---- A tile [64][128] with fused pre-transform. 1024 chunks of 16B.
#pragma unroll
        for (int i = 0; i < 4; i++) {
            int chunk = i * 256 + tid;
            int row = chunk >> 4, cn = chunk & 15;
            int grow = r0 + row;
            union { uint4 u; __half2 h[4]; } pk;
            if (grow >= NODES) {
                pk.u = make_uint4(0, 0, 0, 0);
            } else if (use_pre) {
                union { uint4 u; __half2 h[4]; } in;
                in.u = *(const uint4*)(g_aggh + grow * 128 + cn * 8);
                float di = g_dinv[grow];
                const float* bp = bias + cn * 8;
                float2 f0 = __half22float2(in.h[0]);
                float2 f1 = __half22float2(in.h[1]);
                float2 f2 = __half22float2(in.h[2]);
                float2 f3 = __half22float2(in.h[3]);
                f0.x = fmaxf(fmaf(f0.x, di, bp[0]), 0.f);
                f0.y = fmaxf(fmaf(f0.y, di, bp[1]), 0.f);
                f1.x = fmaxf(fmaf(f1.x, di, bp[2]), 0.f);
                f1.y = fmaxf(fmaf(f1.y, di, bp[3]), 0.f);
                f2.x = fmaxf(fmaf(f2.x, di, bp[4]), 0.f);
                f2.y = fmaxf(fmaf(f2.y, di, bp[5]), 0.f);
                f3.x = fmaxf(fmaf(f3.x, di, bp[6]), 0.f);
                f3.y = fmaxf(fmaf(f3.y, di, bp[7]), 0.f);
                pk.h[0] = __floats2half2_rn(f0.x, f0.y);
                pk.h[1] = __floats2half2_rn(f1.x, f1.y);
                pk.h[2] = __floats2half2_rn(f2.x, f2.y);
                pk.h[3] = __floats2half2_rn(f3.x, f3.y);
            } else {
                float4 v0 = ((const float4*)xin)[grow * 32 + cn * 2];
                float4 v1 = ((const float4*)xin)[grow * 32 + cn * 2 + 1];
                pk.h[0] = __floats2half2_rn(v0.x, v0.y);
                pk.h[1] = __floats2half2_rn(v0.z, v0.w);
                pk.h[2] = __floats2half2_rn(v1.x, v1.y);
                pk.h[3] = __floats2half2_rn(v1.z, v1.w);
            }
            *(uint4*)(sA + row * 128 + ((cn ^ (row & 7)) << 3)) = pk.u;
        }
        __syncthreads();

        float c[2][4][4];
#pragma unroll
        for (int mt = 0; mt < 2; mt++)
#pragma unroll
            for (int nt = 0; nt < 4; nt++)
#pragma unroll
                for (int q = 0; q < 4; q++) c[mt][nt][q] = 0.f;

#pragma unroll
        for (int ks = 0; ks < 8; ks++) {
            uint32_t a[2][4];
#pragma unroll
            for (int mt = 0; mt < 2; mt++) {
                int r = wm * 32 + mt * 16 + (lane & 15);
                int ch = ks * 2 + (lane >> 4);
                uint32_t addr = sAu + (r << 8) + ((ch ^ (r & 7)) << 4);
                asm volatile("ldmatrix.sync.aligned.m8n8.x4.shared.b16 {%0,%1,%2,%3}, [%4];"
                             : "=r"(a[mt][0]), "=r"(a[mt][1]), "=r"(a[mt][2]), "=r"(a[mt][3])
                             : "r"(addr));
            }
            uint32_t b[4][2];
#pragma unroll
            for (int nt = 0; nt < 4; nt++) {
                int r = ks * 16 + (lane & 15);
                int ch = wn * 4 + nt;
                uint32_t addr = sBu + (r << 8) + ((ch ^ (r & 7)) << 4);
                asm volatile("ldmatrix.sync.aligned.m8n8.x2.trans.shared.b16 {%0,%1}, [%2];"
                             : "=r"(b[nt][0]), "=r"(b[nt][1])
                             : "r"(addr));
            }
#pragma unroll
            for (int mt = 0; mt < 2; mt++)
#pragma unroll
                for (int nt = 0; nt < 4; nt++) {
                    asm volatile(
                        "mma.sync.aligned.m16n8k16.row.col.f32.f16.f16.f32 "
                        "{%0,%1,%2,%3}, {%4,%5,%6,%7}, {%8,%9}, {%0,%1,%2,%3};"
                        : "+f"(c[mt][nt][0]), "+f"(c[mt][nt][1]),
                          "+f"(c[mt][nt][2]), "+f"(c[mt][nt][3])
                        : "r"(a[mt][0]), "r"(a[mt][1]), "r"(a[mt][2]), "r"(a[mt][3]),
                          "r"(b[nt][0]), "r"(b[nt][1]));
                }
        }

        // ---- Epilogue: * dinv[row], pack fp16, store.
#pragma unroll
        for (int mt = 0; mt < 2; mt++) {
            int Rb = r0 + wm * 32 + mt * 16 + (lane >> 2);
#pragma unroll
            for (int hf = 0; hf < 2; hf++) {
                int R = Rb + hf * 8;
                if (R < NODES) {
                    float di = g_dinv[R];
#pragma unroll
                    for (int nt = 0; nt < 4; nt++) {
                        int C = wn * 32 + nt * 8 + (lane & 3) * 2;
                        __half2 h = __floats2half2_rn(c[mt][nt][hf * 2 + 0] * di,
                                                      c[mt][nt][hf * 2 + 1] * di);
                        *(__half2*)(g_mh + R * 128 + C) = h;
                    }
                }
            }
        }
    }
}

// ---------------------------------------------------------------------------
// CSR aggregation: agg[n] = m[n] (self loop) + sum_{src in csr row n} m[src].
// One warp per node; 64-thread CTAs (2 warps) to minimize CTA-retire tail
// waste from degree imbalance. Unroll 8. fp32 accumulate, fp16 store.
// ---------------------------------------------------------------------------
__global__ void __launch_bounds__(64) k_aggregate() {
    int node = blockIdx.x * 2 + (threadIdx.x >> 5);
    if (node >= NODES) return;
    int lane = threadIdx.x & 31;

    const __half* mh = g_mh;
    const int* __restrict__ csr = g_csr;

    float a0, a1, a2, a3;
    {   // self loop
        union { uint2 u; __half2 h[2]; } pk;
        pk.u = *(const uint2*)(mh + node * 128 + lane * 4);
        float2 f0 = __half22float2(pk.h[0]);
        float2 f1 = __half22float2(pk.h[1]);
        a0 = f0.x; a1 = f0.y; a2 = f1.x; a3 = f1.y;
    }

    int i = g_rowptr[node];
    int e = i + g_deg[node];

    for (; i + 8 <= e; i += 8) {
        int s[8];
#pragma unroll
        for (int j = 0; j < 8; j++) s[j] = __ldg(csr + i + j);
        union { uint2 u; __half2 h[2]; } p[8];
#pragma unroll
        for (int j = 0; j < 8; j++)
            p[j].u = *(const uint2*)(mh + s[j] * 128 + lane * 4);
#pragma unroll
        for (int j = 0; j < 8; j++) {
            float2 f;
            f = __half22float2(p[j].h[0]); a0 += f.x; a1 += f.y;
            f = __half22float2(p[j].h[1]); a2 += f.x; a3 += f.y;
        }
    }
    for (; i + 2 <= e; i += 2) {
        int s0 = __ldg(csr + i), s1 = __ldg(csr + i + 1);
        union { uint2 u; __half2 h[2]; } p0, p1;
        p0.u = *(const uint2*)(mh + s0 * 128 + lane * 4);
        p1.u = *(const uint2*)(mh + s1 * 128 + lane * 4);
        float2 f;
        f = __half22float2(p0.h[0]); a0 += f.x; a1 += f.y;
        f = __half22float2(p0.h[1]); a2 += f.x; a3 += f.y;
        f = __half22float2(p1.h[0]); a0 += f.x; a1 += f.y;
        f = __half22float2(p1.h[1]); a2 += f.x; a3 += f.y;
    }
    if (i < e) {
        int s0 = __ldg(csr + i);
        union { uint2 u; __half2 h[2]; } p0;
        p0.u = *(const uint2*)(mh + s0 * 128 + lane * 4);
        float2 f;
        f = __half22float2(p0.h[0]); a0 += f.x; a1 += f.y;
        f = __half22float2(p0.h[1]); a2 += f.x; a3 += f.y;
    }

    union { uint2 u; __half2 h[2]; } outp;
    outp.h[0] = __floats2half2_rn(a0, a1);
    outp.h[1] = __floats2half2_rn(a2, a3);
    *(uint2*)(g_aggh + node * 128 + lane * 4) = outp.u;
}

// ---------------------------------------------------------------------------
// Fused mean pool + head: block per graph, 128 threads.
// ---------------------------------------------------------------------------
__global__ void __launch_bounds__(128) k_pool_head(const int* __restrict__ batch,
                                                   const float* __restrict__ b3,
                                                   const float* __restrict__ Wl,
                                                   const float* __restrict__ bl,
                                                   float* __restrict__ out) {
    __shared__ float hg[DH];
    int g = blockIdx.x, t = threadIdx.x;
    int lo = 0, hi = NODES;
    while (lo < hi) { int m = (lo + hi) >> 1; if (batch[m] < g) lo = m + 1; else hi = m; }
    int s = lo;
    hi = NODES;
    while (lo < hi) { int m = (lo + hi) >> 1; if (batch[m] <= g) lo = m + 1; else hi = m; }
    int e = lo;

    float sum = 0.f;
    for (int n = s; n < e; n++)
        sum = fmaf(__half2float(g_aggh[n * 128 + t]), g_dinv[n], sum);
    int cnt = e - s;
    hg[t] = (cnt > 0) ? (sum / (float)cnt + b3[t]) : 0.f;
    __syncthreads();

    if (t < 32) {
        int lane = t;
        float acc[DOUT];
#pragma unroll
        for (int c = 0; c < DOUT; c++) acc[c] = 0.f;
        for (int k = lane; k < DH; k += 32) {
            float h = hg[k];
#pragma unroll
            for (int c = 0; c < DOUT; c++) acc[c] = fmaf(h, Wl[k * DOUT + c], acc[c]);
        }
#pragma unroll
        for (int off = 16; off > 0; off >>= 1)
#pragma unroll
            for (int c = 0; c < DOUT; c++)
                acc[c] += __shfl_xor_sync(0xFFFFFFFFu, acc[c], off);

        float mx = -1e30f;
#pragma unroll
        for (int c = 0; c < DOUT; c++) { acc[c] += bl[c]; mx = fmaxf(mx, acc[c]); }
        float ssum = 0.f;
#pragma unroll
        for (int c = 0; c < DOUT; c++) { acc[c] = expf(acc[c] - mx); ssum += acc[c]; }
        if (lane < DOUT) out[g * DOUT + lane] = acc[lane] / ssum;
    }
}

// ---------------------------------------------------------------------------
extern "C" void kernel_launch(void* const* d_in, const int* in_sizes, int n_in,
                              void* d_out, int out_size) {
    const float* x     = (const float*)d_in[0];
    const int*   ei    = (const int*)  d_in[1];
    const int*   batch = (const int*)  d_in[2];
    const float* W1 = (const float*)d_in[3];
    const float* b1 = (const float*)d_in[4];
    const float* W2 = (const float*)d_in[5];
    const float* b2 = (const float*)d_in[6];
    const float* W3 = (const float*)d_in[7];
    const float* b3 = (const float*)d_in[8];
    const float* Wl = (const float*)d_in[9];
    const float* bl = (const float*)d_in[10];
    float* out = (float*)d_out;

    const int gemm_grid = (NODES + 127) / 128;
    const int agg_grid  = (NODES + 1) / 2;

    // weights (independent of graph structure work below)
    k_wconv_all<<<24, 256>>>(W1, W2, W3);

    // degrees
    k_zero_deg <<<(NODES + 255) / 256, 256>>>();
    k_count_deg<<<(EDGES / 4 + 255) / 256, 256>>>(ei);

    // CSR: single-kernel allocation + fill
    k_alloc    <<<NB, 256>>>();
    k_csr_fill <<<(EDGES / 4 + 255) / 256, 256>>>(ei);

    // Layer 1
    k_gemm_tc  <<<gemm_grid, 256>>>(x, 0, 0, nullptr);
    k_aggregate<<<agg_grid, 64>>>();
    // Layer 2
    k_gemm_tc  <<<gemm_grid, 256>>>(nullptr, 1, 1, b1);
    k_aggregate<<<agg_grid, 64>>>();
    // Layer 3
    k_gemm_tc  <<<gemm_grid, 256>>>(nullptr, 1, 2, b2);
    k_aggregate<<<agg_grid, 64>>>();

    k_pool_head<<<GRAPHS, 128>>>(batch, b3, Wl, bl, out);
}